// round 15
// baseline (speedup 1.0000x reference)
#include <cuda_runtime.h>
#include <math_constants.h>
#include <cstdint>

// Problem constants (from reference setup_inputs)
static constexpr int NB  = 16;   // batch
static constexpr int CIN = 32;   // input channels
static constexpr int DIN = 16;
static constexpr int HIN = 32;
static constexpr int WIN = 32;
static constexpr int ODp = 5;    // pooled output dims
static constexpr int OHp = 10;
static constexpr int OWp = 10;

// 8 chunks of 4 channels, double-buffered; each warp computes 2 (its half).
static constexpr int CHUNK  = 4;
static constexpr int NCHUNK = 8;
static constexpr int CPG    = 2;                      // channels per warp-group
static constexpr int LWP    = 33;                     // padded x row (conflict-free)
static constexpr int XBUF   = CHUNK * 5 * 5 * LWP;    // 3300 floats per buffer
static constexpr int SMEM_FLOATS = 2 * XBUF;          // 6600 (PM2/PMM alias inside)
static constexpr int SMEM_BYTES  = SMEM_FLOATS * 4;   // 26,400 B -> 6 CTAs/SM
static constexpr int PM2_ELEMS = 2 * 2 * 30 * 36;     // 4320 (< 6600, aliases XS)

// wsum padded: [c][kd*5+kh][8] (5 kw + 3 ZERO pads -> {W4,0} 64-bit loads);
// [6400] = bias_sum
__device__ float g_wsum_pad[6404];

typedef unsigned long long ull;

#define FMA2(d, a, b) \
    asm("fma.rn.f32x2 %0, %1, %2, %0;" : "+l"(d) : "l"(a), "l"(b))

__device__ __forceinline__ ull bcast2(float x) {
    ull r;
    asm("mov.b64 %0, {%1, %1};" : "=l"(r) : "f"(x));
    return r;
}
__device__ __forceinline__ float2 unpack2(ull v) {
    float lo, hi;
    asm("mov.b64 {%0, %1}, %2;" : "=f"(lo), "=f"(hi) : "l"(v));
    return make_float2(lo, hi);
}
__device__ __forceinline__ uint32_t smem_u32(const void* p) {
    uint32_t a;
    asm("{ .reg .u64 t; cvta.to.shared.u64 t, %1; cvt.u32.u64 %0, t; }"
        : "=r"(a) : "l"(p));
    return a;
}
// 4-byte async copy with zero-fill: copies min(ssz,4) bytes, zero-fills rest.
__device__ __forceinline__ void cp4_zfill(uint32_t saddr, const void* gptr, int ssz) {
    asm volatile("cp.async.ca.shared.global [%0], [%1], 4, %2;"
                 :: "r"(saddr), "l"(gptr), "r"(ssz) : "memory");
}
__device__ __forceinline__ void cp_commit() {
    asm volatile("cp.async.commit_group;" ::: "memory");
}
template <int N>
__device__ __forceinline__ void cp_wait() {
    asm volatile("cp.async.wait_group %0;" :: "n"(N) : "memory");
}

// ---------------------------------------------------------------------------
// Kernel 1: one block per channel c. Coalesced float4 load of the whole
// (64,5,5,5) weight slice into smem, then per-k reduction over o.
// weight layout: (32,64,5,5,5) -> c*8000 + o*125 + k
// ---------------------------------------------------------------------------
__global__ void prep_kernel(const float* __restrict__ weight,
                            const float* __restrict__ bias) {
    __shared__ float sw[8000];
    const int c = blockIdx.x;
    const int t = threadIdx.x;           // 256
    const float4* src = reinterpret_cast<const float4*>(weight + c * 8000);
    #pragma unroll
    for (int i = t; i < 2000; i += 256)
        reinterpret_cast<float4*>(sw)[i] = src[i];
    __syncthreads();

    if (t < 125) {
        float s = 0.f;
        #pragma unroll
        for (int o = 0; o < 64; o++) s += sw[o * 125 + t];
        g_wsum_pad[c * 200 + (t / 5) * 8 + (t % 5)] = s;
    } else if (t >= 128 && t < 203) {     // zero the 25*3 pad slots
        int i = t - 128;
        int row = i / 3, col = 5 + i - row * 3;
        g_wsum_pad[c * 200 + row * 8 + col] = 0.f;
    } else if (c == 0 && t == 255) {
        float bs = 0.f;
        #pragma unroll
        for (int o = 0; o < 64; o++) bs += bias[o];
        g_wsum_pad[6400] = bs;
    }
}

// ---------------------------------------------------------------------------
// Per-chunk compute for oh-parity PB, channels [C0, C0+CPG) of this chunk.
// Thread owns all 6 od x 6 ow = 36 y partials as 18 f32x2 accumulators
// acc[od*3 + owpair].  Identity: od = 2*ld + kd - 4, valid in [0,5].
// Each X row is loaded once (5 LDS) and applied to all valid kd taps.
// Weights read as warp-uniform 64-bit __ldg broadcasts from g_wsum_pad.
// ---------------------------------------------------------------------------
template <int PB>
__device__ __forceinline__ void compute_chunk(const float* __restrict__ XS,
                                              const float* __restrict__ gw,
                                              int C0, int b_off, int w,
                                              ull (&acc)[18]) {
    constexpr int NT = 3 - PB;   // # kh taps
    const int xcol = 3 * w;

    #pragma unroll
    for (int cc = 0; cc < CPG; cc++) {
        const float* XC = XS + (C0 + cc) * (25 * LWP);
        const float* WC = gw + (C0 + cc) * 200;
        #pragma unroll
        for (int t = 0; t < NT; t++) {
            const int lh = b_off + 2 - t;
            const int kh = PB + 2 * t;
            // Hoist all 5 kd weight rows for this kh (uniform 64-bit LDG).
            ull W01[5], W23[5], W40[5];
            #pragma unroll
            for (int kd = 0; kd < 5; kd++) {
                const ull* wr = reinterpret_cast<const ull*>(
                    WC + (kd * 5 + kh) * 8);
                W01[kd] = __ldg(wr);
                W23[kd] = __ldg(wr + 1);
                W40[kd] = __ldg(wr + 2);   // {W4, 0} thanks to zero padding
            }
            #pragma unroll
            for (int ld = 0; ld < 5; ld++) {
                const float* Xr = XC + (ld * 5 + lh) * LWP + xcol;
                const ull XX0 = bcast2(Xr[0]);
                const ull XX1 = bcast2(Xr[1]);
                const ull XX2 = bcast2(Xr[2]);
                const ull XX3 = bcast2(Xr[3]);
                const ull XX4 = bcast2(Xr[4]);
                #pragma unroll
                for (int kd = 0; kd < 5; kd++) {
                    const int od = 2 * ld + kd - 4;
                    if (od < 0 || od > 5) continue;   // folds at compile time
                    ull* P = acc + od * 3;
                    FMA2(P[0], XX2, W01[kd]);
                    FMA2(P[0], XX1, W23[kd]);
                    FMA2(P[0], XX0, W40[kd]);
                    FMA2(P[1], XX3, W01[kd]);
                    FMA2(P[1], XX2, W23[kd]);
                    FMA2(P[1], XX1, W40[kd]);
                    FMA2(P[2], XX4, W01[kd]);
                    FMA2(P[2], XX3, W23[kd]);
                    FMA2(P[2], XX2, W40[kd]);
                }
            }
        }
    }
}

// ---------------------------------------------------------------------------
// Kernel 2: fused transposed-conv (channel-summed) + 6x6x6/6 max pool.
// Block = (n, d, h); 128 threads = 4 warps = (pb, channel-half); pb mapping
// swapped by block parity so SMSPs average the pb0/pb1 load across CTAs.
// Double-buffered cp.async staging: chunk k+2 prefetched during chunk k.
// Reduction arrays alias the X buffers (only live after the last compute).
// ---------------------------------------------------------------------------
__global__ __launch_bounds__(128, 6)
void fused_kernel(const float* __restrict__ x, float* __restrict__ out) {
    extern __shared__ float smem[];

    const int h = blockIdx.x;
    const int d = blockIdx.y;
    const int n = blockIdx.z;
    const int tid   = threadIdx.x;
    const int wid   = tid >> 5;
    const int lane  = tid & 31;
    const int par   = (blockIdx.x + blockIdx.y + blockIdx.z) & 1;
    const int pb    = (wid >> 1) ^ par;    // oh parity (block-parity swapped)
    const int group = wid & 1;             // channel half of each 4-chunk
    const int C0    = group * CPG;
    const int b_off = lane / 10;           // 0..2 (lanes 30,31: garbage, unstored)
    const int w     = lane - b_off * 10;

    const int id0 = 3 * d - 1;
    const int ih0 = 3 * h - 1;
    const float* xn = x + (long)n * (CIN * DIN * HIN * WIN);
    const uint32_t xs_base = smem_u32(smem);
    // Per-thread staging dst base (affine in rr: + rr*528, per-channel +3300B*... )
    const uint32_t dbase = xs_base + (wid * LWP + 1 + lane) * 4;

    // goff table: rows r = wid + 4*rr; rr<6 always valid rows, rr=6 only wid==0.
    // Validity folded into sign (negative => zero-fill).
    int goff[7];
    #pragma unroll
    for (int rr = 0; rr < 7; rr++) {
        int r  = wid + 4 * rr;
        int rc = r < 25 ? r : 24;
        int ld = rc / 5;
        int lh = rc - ld * 5;
        int id = id0 + ld;
        int ih = ih0 + lh;
        bool v = (id >= 0) && (ih >= 0);   // upper bounds always in range
        goff[rr] = v ? (id * (HIN * WIN) + ih * WIN + lane) : -1;
    }
    const bool has7 = (wid == 0);          // row 24

    // --- zero the lw=0 pad columns of BOTH buffers (staging never writes them)
    for (int r = tid; r < 2 * CHUNK * 25; r += 128) smem[r * LWP] = 0.f;

    ull acc[18];
    #pragma unroll
    for (int i = 0; i < 18; i++) acc[i] = 0ull;

    // --- staging helper (inlined twice for prologue, once in loop) ---
    auto stage = [&](int buf, int chunk) {
        const float* xsrc = xn + chunk * (CHUNK * DIN * HIN * WIN);
        const uint32_t bb = dbase + buf * (XBUF * 4);
        #pragma unroll
        for (int c = 0; c < CHUNK; c++) {
            const float* gp = xsrc + c * (DIN * HIN * WIN);
            const uint32_t db = bb + c * (25 * LWP * 4);
            #pragma unroll
            for (int rr = 0; rr < 6; rr++) {
                int g = goff[rr];
                cp4_zfill(db + rr * (4 * LWP * 4), gp + (g < 0 ? 0 : g),
                          g < 0 ? 0 : 4);
            }
            if (has7) {
                int g = goff[6];
                cp4_zfill(db + 6 * (4 * LWP * 4), gp + (g < 0 ? 0 : g),
                          g < 0 ? 0 : 4);
            }
        }
        cp_commit();
    };

    stage(0, 0);
    stage(1, 1);

    #pragma unroll 1
    for (int chunk = 0; chunk < NCHUNK; chunk++) {
        if (chunk == NCHUNK - 1) cp_wait<0>(); else cp_wait<1>();
        __syncthreads();                     // chunk's data visible to all warps

        const float* XS = smem + (chunk & 1) * XBUF;
        const float* gw = g_wsum_pad + chunk * (CHUNK * 200);
        if (pb == 0) compute_chunk<0>(XS, gw, C0, b_off, w, acc);
        else         compute_chunk<1>(XS, gw, C0, b_off, w, acc);

        __syncthreads();                     // all warps done with this buffer
        if (chunk + 2 < NCHUNK) stage(chunk & 1, chunk + 2);
    }

    // ---- reduction arrays alias the X buffers from here on ----
    float* PM2 = smem;                       // [2 pb][2 group][30][36]
    float* PMM = smem + PM2_ELEMS;           // [2 pb][30]

    // ---- store this (pb, group) 36 channel-partials for the cell ----
    if (lane < 30) {
        float* P = PM2 + ((pb * 2 + group) * 30 + lane) * 36;
        #pragma unroll
        for (int i = 0; i < 18; i++) {
            float2 v = unpack2(acc[i]);
            P[2 * i]     = v.x;
            P[2 * i + 1] = v.y;
        }
    }
    __syncthreads();

    // ---- per (pb, cell): sum the two channel-groups, max over 36 pts ----
    if (tid < 60) {
        const int p2   = tid / 30;
        const int cell = tid - p2 * 30;
        const float* A = PM2 + (p2 * 2 * 30 + cell) * 36;   // group 0
        const float* B = A + 30 * 36;                        // group 1
        float m = -CUDART_INF_F;
        #pragma unroll
        for (int i = 0; i < 36; i++) m = fmaxf(m, A[i] + B[i]);
        PMM[p2 * 30 + cell] = m;
    }
    __syncthreads();

    // ---- final: max over pb and b_off, add bias_sum, emit ----
    if (tid < OWp) {
        float mm = -CUDART_INF_F;
        #pragma unroll
        for (int p2 = 0; p2 < 2; p2++)
            #pragma unroll
            for (int bo = 0; bo < 3; bo++)
                mm = fmaxf(mm, PMM[p2 * 30 + bo * 10 + tid]);
        const float bs = g_wsum_pad[6400];
        out[(((long)n * ODp + d) * OHp + h) * OWp + tid] = mm + bs;
    }
}

// ---------------------------------------------------------------------------
extern "C" void kernel_launch(void* const* d_in, const int* in_sizes, int n_in,
                              void* d_out, int out_size) {
    (void)in_sizes; (void)n_in; (void)out_size;
    const float* x      = (const float*)d_in[0];
    const float* weight = (const float*)d_in[1];
    const float* bias   = (const float*)d_in[2];
    float* out = (float*)d_out;

    prep_kernel<<<32, 256>>>(weight, bias);
    fused_kernel<<<dim3(OHp, ODp, NB), 128, SMEM_BYTES>>>(x, out);
}

// round 16
// speedup vs baseline: 1.1184x; 1.1184x over previous
#include <cuda_runtime.h>
#include <math_constants.h>
#include <cstdint>

// Problem constants (from reference setup_inputs)
static constexpr int NB  = 16;   // batch
static constexpr int CIN = 32;   // input channels
static constexpr int DIN = 16;
static constexpr int HIN = 32;
static constexpr int WIN = 32;
static constexpr int ODp = 5;    // pooled output dims
static constexpr int OHp = 10;
static constexpr int OWp = 10;

// 4 chunks of 8 channels staged (proven best granularity, R13).
static constexpr int CHUNK = 8;
static constexpr int CPG   = 4;                        // channels per warp-group
static constexpr int LWP   = 33;                       // padded x row (conflict-free)
static constexpr int XS_ELEMS = CHUNK * 5 * 5 * LWP;   // 6600 floats = 26.4 KB
static constexpr int PM2_ELEMS = 2 * 2 * 30 * 36;      // 4320 (aliases XS after compute)
static constexpr int SMEM_BYTES = XS_ELEMS * 4;        // 26,400 B -> smem allows 8 CTAs

// wsum padded: [c][kd*5+kh][8] (5 kw + 3 ZERO pads -> {W4,0} 64-bit loads);
// [6400] = bias_sum
__device__ float g_wsum_pad[6404];

typedef unsigned long long ull;

#define FMA2(d, a, b) \
    asm("fma.rn.f32x2 %0, %1, %2, %0;" : "+l"(d) : "l"(a), "l"(b))

__device__ __forceinline__ ull bcast2(float x) {
    ull r;
    asm("mov.b64 %0, {%1, %1};" : "=l"(r) : "f"(x));
    return r;
}
__device__ __forceinline__ float2 unpack2(ull v) {
    float lo, hi;
    asm("mov.b64 {%0, %1}, %2;" : "=f"(lo), "=f"(hi) : "l"(v));
    return make_float2(lo, hi);
}
__device__ __forceinline__ uint32_t smem_u32(const void* p) {
    uint32_t a;
    asm("{ .reg .u64 t; cvta.to.shared.u64 t, %1; cvt.u32.u64 %0, t; }"
        : "=r"(a) : "l"(p));
    return a;
}
// 4-byte async copy with zero-fill: copies min(ssz,4) bytes, zero-fills rest.
__device__ __forceinline__ void cp4_zfill(uint32_t saddr, const void* gptr, int ssz) {
    asm volatile("cp.async.ca.shared.global [%0], [%1], 4, %2;"
                 :: "r"(saddr), "l"(gptr), "r"(ssz) : "memory");
}
__device__ __forceinline__ void cp_async_commit_wait_all() {
    asm volatile("cp.async.commit_group;" ::: "memory");
    asm volatile("cp.async.wait_group 0;" ::: "memory");
}

// ---------------------------------------------------------------------------
// Kernel 1: one block per channel c. Coalesced float4 load of the whole
// (64,5,5,5) weight slice into smem, then per-k reduction over o.
// weight layout: (32,64,5,5,5) -> c*8000 + o*125 + k
// ---------------------------------------------------------------------------
__global__ void prep_kernel(const float* __restrict__ weight,
                            const float* __restrict__ bias) {
    __shared__ float sw[8000];
    const int c = blockIdx.x;
    const int t = threadIdx.x;           // 256
    const float4* src = reinterpret_cast<const float4*>(weight + c * 8000);
    #pragma unroll
    for (int i = t; i < 2000; i += 256)
        reinterpret_cast<float4*>(sw)[i] = src[i];
    __syncthreads();

    if (t < 125) {
        float s = 0.f;
        #pragma unroll
        for (int o = 0; o < 64; o++) s += sw[o * 125 + t];
        g_wsum_pad[c * 200 + (t / 5) * 8 + (t % 5)] = s;
    } else if (t >= 128 && t < 203) {     // zero the 25*3 pad slots
        int i = t - 128;
        int row = i / 3, col = 5 + i - row * 3;
        g_wsum_pad[c * 200 + row * 8 + col] = 0.f;
    } else if (c == 0 && t == 255) {
        float bs = 0.f;
        #pragma unroll
        for (int o = 0; o < 64; o++) bs += bias[o];
        g_wsum_pad[6400] = bs;
    }
}

// ---------------------------------------------------------------------------
// Per-chunk compute for oh-parity PB, channels [C0, C0+CPG).
// Thread owns all 6 od x 6 ow = 36 y partials as 18 f32x2 accumulators
// acc[od*3 + owpair].  Identity: od = 2*ld + kd - 4, valid in [0,5].
// Each X row is loaded once (5 LDS) and applied to all valid kd taps.
// Weights read as warp-uniform 64-bit __ldg broadcasts from g_wsum_pad.
// ---------------------------------------------------------------------------
template <int PB>
__device__ __forceinline__ void compute_chunk(const float* __restrict__ XS,
                                              const float* __restrict__ gw,
                                              int C0, int b_off, int w,
                                              ull (&acc)[18]) {
    constexpr int NT = 3 - PB;   // # kh taps
    const int xcol = 3 * w;

    for (int c = C0; c < C0 + CPG; c++) {
        const float* XC = XS + c * (25 * LWP);
        const float* WC = gw + c * 200;
        #pragma unroll
        for (int t = 0; t < NT; t++) {
            const int lh = b_off + 2 - t;
            const int kh = PB + 2 * t;
            // Hoist all 5 kd weight rows for this kh (uniform 64-bit LDG).
            ull W01[5], W23[5], W40[5];
            #pragma unroll
            for (int kd = 0; kd < 5; kd++) {
                const ull* wr = reinterpret_cast<const ull*>(
                    WC + (kd * 5 + kh) * 8);
                W01[kd] = __ldg(wr);
                W23[kd] = __ldg(wr + 1);
                W40[kd] = __ldg(wr + 2);   // {W4, 0} thanks to zero padding
            }
            #pragma unroll
            for (int ld = 0; ld < 5; ld++) {
                const float* Xr = XC + (ld * 5 + lh) * LWP + xcol;
                const ull XX0 = bcast2(Xr[0]);
                const ull XX1 = bcast2(Xr[1]);
                const ull XX2 = bcast2(Xr[2]);
                const ull XX3 = bcast2(Xr[3]);
                const ull XX4 = bcast2(Xr[4]);
                #pragma unroll
                for (int kd = 0; kd < 5; kd++) {
                    const int od = 2 * ld + kd - 4;
                    if (od < 0 || od > 5) continue;   // folds at compile time
                    ull* P = acc + od * 3;
                    FMA2(P[0], XX2, W01[kd]);
                    FMA2(P[0], XX1, W23[kd]);
                    FMA2(P[0], XX0, W40[kd]);
                    FMA2(P[1], XX3, W01[kd]);
                    FMA2(P[1], XX2, W23[kd]);
                    FMA2(P[1], XX1, W40[kd]);
                    FMA2(P[2], XX4, W01[kd]);
                    FMA2(P[2], XX3, W23[kd]);
                    FMA2(P[2], XX2, W40[kd]);
                }
            }
        }
    }
}

// ---------------------------------------------------------------------------
// Kernel 2: fused transposed-conv (channel-summed) + 6x6x6/6 max pool.
// Block = (n, d, h); 128 threads = 4 warps = (pb, channel-half); pb mapping
// swapped by block parity so SMSPs average the pb0/pb1 load across CTAs.
// Synchronous cp.async staging (R13 shape); reduction arrays alias XS.
// ---------------------------------------------------------------------------
__global__ __launch_bounds__(128, 6)
void fused_kernel(const float* __restrict__ x, float* __restrict__ out) {
    extern __shared__ float smem[];
    float* XS = smem;                          // [8][5][5][LWP]

    const int h = blockIdx.x;
    const int d = blockIdx.y;
    const int n = blockIdx.z;
    const int tid   = threadIdx.x;
    const int wid   = tid >> 5;
    const int lane  = tid & 31;
    const int par   = (blockIdx.x + blockIdx.y + blockIdx.z) & 1;
    const int pb    = (wid >> 1) ^ par;    // oh parity (block-parity swapped)
    const int group = wid & 1;             // channel half
    const int C0    = group * CPG;
    const int b_off = lane / 10;           // 0..2 (lanes 30,31: garbage, unstored)
    const int w     = lane - b_off * 10;

    const int id0 = 3 * d - 1;
    const int ih0 = 3 * h - 1;
    const float* xn = x + (long)n * (CIN * DIN * HIN * WIN);
    // Per-thread staging dst base; affine in (c, rr).
    const uint32_t dbase = smem_u32(XS) + (wid * LWP + 1 + lane) * 4;

    // goff table: rows r = wid + 4*rr; rr<6 always in-range rows, rr=6 only
    // wid==0 (row 24). Validity folded into sign (negative => zero-fill).
    int goff[7];
    #pragma unroll
    for (int rr = 0; rr < 7; rr++) {
        int r  = wid + 4 * rr;
        int rc = r < 25 ? r : 24;
        int ld = rc / 5;
        int lh = rc - ld * 5;
        int id = id0 + ld;
        int ih = ih0 + lh;
        bool v = (id >= 0) && (ih >= 0);   // upper bounds always in range
        goff[rr] = v ? (id * (HIN * WIN) + ih * WIN + lane) : -1;
    }
    const bool has7 = (wid == 0);

    // --- zero the lw=0 pad column once; staging never overwrites it ---
    for (int r = tid; r < CHUNK * 25; r += 128) XS[r * LWP] = 0.f;

    ull acc[18];
    #pragma unroll
    for (int i = 0; i < 18; i++) acc[i] = 0ull;

    for (int chunk = 0; chunk < 4; chunk++) {
        if (chunk) __syncthreads();          // protect XS before re-staging
        // ---- stage x chunk (8 ch) via cp.async: lanes 1:1 to iw, coalesced ----
        const float* xc = xn + chunk * (CHUNK * DIN * HIN * WIN);
        #pragma unroll
        for (int c = 0; c < CHUNK; c++) {
            const float* gp = xc + c * (DIN * HIN * WIN);
            const uint32_t db = dbase + c * (25 * LWP * 4);
            #pragma unroll
            for (int rr = 0; rr < 6; rr++) {
                int g = goff[rr];
                cp4_zfill(db + rr * (4 * LWP * 4), gp + (g < 0 ? 0 : g),
                          g < 0 ? 0 : 4);
            }
            if (has7) {
                int g = goff[6];
                cp4_zfill(db + 6 * (4 * LWP * 4), gp + (g < 0 ? 0 : g),
                          g < 0 ? 0 : 4);
            }
        }
        cp_async_commit_wait_all();
        __syncthreads();

        const float* gw = g_wsum_pad + chunk * (CHUNK * 200);
        if (pb == 0) compute_chunk<0>(XS, gw, C0, b_off, w, acc);
        else         compute_chunk<1>(XS, gw, C0, b_off, w, acc);
    }
    __syncthreads();   // all reads of XS complete; reductions may alias it

    // ---- reduction arrays alias XS from here on ----
    float* PM2 = smem;                       // [2 pb][2 group][30][36]
    float* PMM = smem + PM2_ELEMS;           // [2 pb][30]

    // ---- store this (pb, group) 36 channel-partials for the cell ----
    if (lane < 30) {
        float* P = PM2 + ((pb * 2 + group) * 30 + lane) * 36;
        #pragma unroll
        for (int i = 0; i < 18; i++) {
            float2 v = unpack2(acc[i]);
            P[2 * i]     = v.x;
            P[2 * i + 1] = v.y;
        }
    }
    __syncthreads();

    // ---- per (pb, cell): sum the two channel-groups, max over 36 pts ----
    if (tid < 60) {
        const int p2   = tid / 30;
        const int cell = tid - p2 * 30;
        const float* A = PM2 + (p2 * 2 * 30 + cell) * 36;   // group 0
        const float* B = A + 30 * 36;                        // group 1
        float m = -CUDART_INF_F;
        #pragma unroll
        for (int i = 0; i < 36; i++) m = fmaxf(m, A[i] + B[i]);
        PMM[p2 * 30 + cell] = m;
    }
    __syncthreads();

    // ---- final: max over pb and b_off, add bias_sum, emit ----
    if (tid < OWp) {
        float mm = -CUDART_INF_F;
        #pragma unroll
        for (int p2 = 0; p2 < 2; p2++)
            #pragma unroll
            for (int bo = 0; bo < 3; bo++)
                mm = fmaxf(mm, PMM[p2 * 30 + bo * 10 + tid]);
        const float bs = g_wsum_pad[6400];
        out[(((long)n * ODp + d) * OHp + h) * OWp + tid] = mm + bs;
    }
}

// ---------------------------------------------------------------------------
extern "C" void kernel_launch(void* const* d_in, const int* in_sizes, int n_in,
                              void* d_out, int out_size) {
    (void)in_sizes; (void)n_in; (void)out_size;
    const float* x      = (const float*)d_in[0];
    const float* weight = (const float*)d_in[1];
    const float* bias   = (const float*)d_in[2];
    float* out = (float*)d_out;

    prep_kernel<<<32, 256>>>(weight, bias);
    fused_kernel<<<dim3(OHp, ODp, NB), 128, SMEM_BYTES>>>(x, out);
}